// round 10
// baseline (speedup 1.0000x reference)
#include <cuda_runtime.h>

#define BB 4096
#define TT 2048
#define HH 10

union F2U { float2 f; unsigned long long u; };

__device__ __forceinline__ float2 ffma2(float2 a, float2 b, float2 c) {
    F2U ua, ub, uc, ud;
    ua.f = a; ub.f = b; uc.f = c;
    asm("fma.rn.f32x2 %0, %1, %2, %3;" : "=l"(ud.u) : "l"(ua.u), "l"(ub.u), "l"(uc.u));
    return ud.f;
}
__device__ __forceinline__ float2 fmul2(float2 a, float2 b) {
    F2U ua, ub, ud;
    ua.f = a; ub.f = b;
    asm("mul.rn.f32x2 %0, %1, %2;" : "=l"(ud.u) : "l"(ua.u), "l"(ub.u));
    return ud.f;
}
__device__ __forceinline__ float2 fadd2(float2 a, float2 b) {
    F2U ua, ub, ud;
    ua.f = a; ub.f = b;
    asm("add.rn.f32x2 %0, %1, %2;" : "=l"(ud.u) : "l"(ua.u), "l"(ub.u));
    return ud.f;
}
__device__ __forceinline__ float tanh_fast(float x) {
    float y;
    asm("tanh.approx.f32 %0, %1;" : "=f"(y) : "f"(x));
    return y;
}

// One hidden unit per thread, 3 LSTM elements per warp (lanes 0..29).
// 10-warp CTAs, grid=137 -> <=1 CTA/SM, uniform 10 warps/SM.
// Gate dots computed as TRANSPOSED PAIR-CHAINS: accumulator .x carries gate i,
// .y carries gate f (same for g/o), over h values stored DUPLICATED in smem
// ((h,h) pairs via STS.64). No horizontal adds; x-term+bias fold into chain
// init. A plain h copy (STS.32) serves the output projection's pairs.
// Activations MUFU.TANH (sigmoid 0.5-scale folded into weights/biases).
// One STG.128 per 4 steps; x via float4; double-buffered, no syncwarp
// (warp converged, per-warp SMEM pipe in-order).
__global__ void __launch_bounds__(320, 1) lstm_fused_kernel(
    const float* __restrict__ x,      // [B, T, 1]
    const float* __restrict__ W_ih,   // [4H, 1]
    const float* __restrict__ W_hh,   // [4H, H]
    const float* __restrict__ b_ih,   // [4H]
    const float* __restrict__ b_hh,   // [4H]
    const float* __restrict__ W_out,  // [1, H]
    const float* __restrict__ b_out,  // [1]
    float* __restrict__ out)          // [B, T, 1]
{
    // duplicated h: [buf][warp][slot][24]  (20 used; slot 3 = scratch)
    __shared__ float hdup[2][10][4][24];
    // plain h:      [buf][warp][slot][12]  (10 used; slot 3 = scratch)
    __shared__ float hpl[2][10][4][12];

    const int tid  = threadIdx.x;
    const int lane = tid & 31;
    const int w    = tid >> 5;

    int ew = lane / HH;              // 0..2 element, 3 = idle lanes 30,31
    int j  = lane - ew * HH;         // hidden unit 0..9 (idle: 0,1)
    bool active = (ew < 3);

    int b = (blockIdx.x * 10 + w) * 3 + ew;
    if (b >= BB) active = false;
    const int bb = active ? b : 0;

    // zero this warp's exchange buffers (h0 = 0 and scratch)
    for (int i = lane; i < 4 * 24; i += 32) {
        hdup[0][w][0][i] = 0.0f;  hdup[1][w][0][i] = 0.0f;
    }
    for (int i = lane; i < 4 * 12; i += 32) {
        hpl[0][w][0][i] = 0.0f;   hpl[1][w][0][i] = 0.0f;
    }
    // no cross-warp smem dependency: each warp only touches [.][w][.][.]

    // ---- per-thread constants ----
    // pair weights: wif[k] = (0.5*Wi[j][k], 0.5*Wf[j][k]); wgo[k] = (Wg[j][k], 0.5*Wo[j][k])
    float2 wif[HH], wgo[HH], wout2[5];
#pragma unroll
    for (int k = 0; k < HH; k++) {
        wif[k] = make_float2(0.5f * W_hh[(0 * HH + j) * HH + k],
                             0.5f * W_hh[(1 * HH + j) * HH + k]);
        wgo[k] = make_float2(W_hh[(2 * HH + j) * HH + k],
                             0.5f * W_hh[(3 * HH + j) * HH + k]);
    }
#pragma unroll
    for (int m = 0; m < 5; m++)
        wout2[m] = make_float2(W_out[2 * m], W_out[2 * m + 1]);

    const float2 wxif = make_float2(0.5f * W_ih[0 * HH + j], 0.5f * W_ih[1 * HH + j]);
    const float2 wxgo = make_float2(       W_ih[2 * HH + j], 0.5f * W_ih[3 * HH + j]);
    const float2 bif  = make_float2(0.5f * (b_ih[0 * HH + j] + b_hh[0 * HH + j]),
                                    0.5f * (b_ih[1 * HH + j] + b_hh[1 * HH + j]));
    const float2 bgo  = make_float2(       (b_ih[2 * HH + j] + b_hh[2 * HH + j]),
                                    0.5f * (b_ih[3 * HH + j] + b_hh[3 * HH + j]));
    const float2 bout2 = make_float2(b_out[0], 0.0f);

    const float* xp = x   + (size_t)bb * TT;
    float*       op = out + (size_t)bb * TT;
    const bool do_out = active && (j == 0);

    const float* rdD0 = &hdup[0][w][ew][0];
    const float* rdD1 = &hdup[1][w][ew][0];
    const float* rdP0 = &hpl[0][w][ew][0];
    const float* rdP1 = &hpl[1][w][ew][0];
    float* wrD0 = &hdup[0][w][ew][2 * j];
    float* wrD1 = &hdup[1][w][ew][2 * j];
    float* wrP0 = &hpl[0][w][ew][j];
    float* wrP1 = &hpl[1][w][ew][j];

    float c = 0.0f;
    float4 obuf;

    // One step: reads h[t-1] (dup + plain), writes h[t], returns proj of h[t-1].
    auto step = [&](float xv,
                    const float* rdD, const float* rdP,
                    float* wrD, float* wrP) -> float {
        // duplicated pairs: D[i].xy = (h_{2i},h_{2i}), D[i].zw = (h_{2i+1},h_{2i+1})
        float4 D0 = *(const float4*)(rdD + 0);
        float4 D1 = *(const float4*)(rdD + 4);
        float4 D2 = *(const float4*)(rdD + 8);
        float4 D3 = *(const float4*)(rdD + 12);
        float4 D4 = *(const float4*)(rdD + 16);
        // plain pairs for projection
        float4 P0 = *(const float4*)(rdP + 0);
        float4 P1 = *(const float4*)(rdP + 4);
        float2 P2 = *(const float2*)(rdP + 8);

        // projection of h[t-1]
        float2 oacc = ffma2(make_float2(P0.x, P0.y), wout2[0], bout2);
        oacc = ffma2(make_float2(P0.z, P0.w), wout2[1], oacc);
        oacc = ffma2(make_float2(P1.x, P1.y), wout2[2], oacc);
        oacc = ffma2(make_float2(P1.z, P1.w), wout2[3], oacc);
        oacc = ffma2(P2, wout2[4], oacc);

        float2 x2 = make_float2(xv, xv);

        // IF pair: .x accumulates gate i, .y gate f (both pre-scaled by 0.5)
        float2 ifA = ffma2(x2, wxif, bif);
        ifA = ffma2(make_float2(D0.x, D0.y), wif[0], ifA);
        ifA = ffma2(make_float2(D0.z, D0.w), wif[1], ifA);
        ifA = ffma2(make_float2(D1.x, D1.y), wif[2], ifA);
        ifA = ffma2(make_float2(D1.z, D1.w), wif[3], ifA);
        ifA = ffma2(make_float2(D2.x, D2.y), wif[4], ifA);
        float2 ifB = fmul2(make_float2(D2.z, D2.w), wif[5]);
        ifB = ffma2(make_float2(D3.x, D3.y), wif[6], ifB);
        ifB = ffma2(make_float2(D3.z, D3.w), wif[7], ifB);
        ifB = ffma2(make_float2(D4.x, D4.y), wif[8], ifB);
        ifB = ffma2(make_float2(D4.z, D4.w), wif[9], ifB);
        float2 aIF = fadd2(ifA, ifB);

        // GO pair: .x gate g (unscaled), .y gate o (pre-scaled by 0.5)
        float2 goA = ffma2(x2, wxgo, bgo);
        goA = ffma2(make_float2(D0.x, D0.y), wgo[0], goA);
        goA = ffma2(make_float2(D0.z, D0.w), wgo[1], goA);
        goA = ffma2(make_float2(D1.x, D1.y), wgo[2], goA);
        goA = ffma2(make_float2(D1.z, D1.w), wgo[3], goA);
        goA = ffma2(make_float2(D2.x, D2.y), wgo[4], goA);
        float2 goB = fmul2(make_float2(D2.z, D2.w), wgo[5]);
        goB = ffma2(make_float2(D3.x, D3.y), wgo[6], goB);
        goB = ffma2(make_float2(D3.z, D3.w), wgo[7], goB);
        goB = ffma2(make_float2(D4.x, D4.y), wgo[8], goB);
        goB = ffma2(make_float2(D4.z, D4.w), wgo[9], goB);
        float2 aGO = fadd2(goA, goB);

        float si = fmaf(tanh_fast(aIF.x), 0.5f, 0.5f);
        float sf = fmaf(tanh_fast(aIF.y), 0.5f, 0.5f);
        float g  =      tanh_fast(aGO.x);
        float so = fmaf(tanh_fast(aGO.y), 0.5f, 0.5f);
        c = fmaf(sf, c, si * g);
        float h = so * tanh_fast(c);

        *(float2*)wrD = make_float2(h, h);   // STS.64 duplicated
        *wrP = h;                            // STS.32 plain
        return oacc.x + oacc.y;
    };

    // ---- t = 0..3: buf parity 0,1,0,1; first projection (h=-1) discarded ----
    float4 x4 = *(const float4*)xp;
    float4 xn4 = *(const float4*)(xp + 4);
    (void)step(x4.x, rdD0, rdP0, wrD1, wrP1);
    obuf.x = step(x4.y, rdD1, rdP1, wrD0, wrP0);    // out[0]
    obuf.y = step(x4.z, rdD0, rdP0, wrD1, wrP1);    // out[1]
    obuf.z = step(x4.w, rdD1, rdP1, wrD0, wrP0);    // out[2]
    x4 = xn4;

    // ---- blocks 1..510: unconditional prefetch of block u+1 ----
#pragma unroll 2
    for (int u = 1; u < TT / 4 - 1; u++) {
        xn4 = *(const float4*)(xp + 4 * u + 4);
        obuf.w = step(x4.x, rdD0, rdP0, wrD1, wrP1);   // out[4u-1]
        if (do_out) *(float4*)(op + 4 * u - 4) = obuf;
        obuf.x = step(x4.y, rdD1, rdP1, wrD0, wrP0);   // out[4u]
        obuf.y = step(x4.z, rdD0, rdP0, wrD1, wrP1);   // out[4u+1]
        obuf.z = step(x4.w, rdD1, rdP1, wrD0, wrP0);   // out[4u+2]
        x4 = xn4;
    }

    // ---- peeled last block u = 511 (t = 2044..2047) ----
    {
        const int u = TT / 4 - 1;
        obuf.w = step(x4.x, rdD0, rdP0, wrD1, wrP1);
        if (do_out) *(float4*)(op + 4 * u - 4) = obuf;
        obuf.x = step(x4.y, rdD1, rdP1, wrD0, wrP0);
        obuf.y = step(x4.z, rdD0, rdP0, wrD1, wrP1);
        obuf.z = step(x4.w, rdD1, rdP1, wrD0, wrP0);
    }

    // ---- final: out[T-1] from h[T-1] (plain buf 0) ----
    {
        float4 P0 = *(const float4*)(rdP0 + 0);
        float4 P1 = *(const float4*)(rdP0 + 4);
        float2 P2 = *(const float2*)(rdP0 + 8);
        float2 oacc = ffma2(make_float2(P0.x, P0.y), wout2[0], bout2);
        oacc = ffma2(make_float2(P0.z, P0.w), wout2[1], oacc);
        oacc = ffma2(make_float2(P1.x, P1.y), wout2[2], oacc);
        oacc = ffma2(make_float2(P1.z, P1.w), wout2[3], oacc);
        oacc = ffma2(P2, wout2[4], oacc);
        obuf.w = oacc.x + oacc.y;
        if (do_out) *(float4*)(op + TT - 4) = obuf;
    }
}

extern "C" void kernel_launch(void* const* d_in, const int* in_sizes, int n_in,
                              void* d_out, int out_size) {
    const float* x     = (const float*)d_in[0];
    const float* W_ih  = (const float*)d_in[1];
    const float* W_hh  = (const float*)d_in[2];
    const float* b_ih  = (const float*)d_in[3];
    const float* b_hh  = (const float*)d_in[4];
    const float* W_out = (const float*)d_in[5];
    const float* b_out = (const float*)d_in[6];
    float* out = (float*)d_out;

    // 10-warp CTAs, 30 elements each: 137 CTAs -> <=1 CTA/SM, uniform 10 warps/SM
    const int elems_per_block = 30;
    const int grid = (BB + elems_per_block - 1) / elems_per_block;  // 137
    lstm_fused_kernel<<<grid, 320>>>(x, W_ih, W_hh, b_ih, b_hh, W_out, b_out, out);
}

// round 14
// speedup vs baseline: 1.2150x; 1.2150x over previous
#include <cuda_runtime.h>

#define BB 4096
#define TT 2048
#define HH 10
#define NSLOT 10
#define SLOTF 484   // floats per ring slot (480 used + 4 pad; 16B-aligned, odd mod 32 grp)

union F2U { float2 f; unsigned long long u; };

__device__ __forceinline__ float2 ffma2(float2 a, float2 b, float2 c) {
    F2U ua, ub, uc, ud;
    ua.f = a; ub.f = b; uc.f = c;
    asm("fma.rn.f32x2 %0, %1, %2, %3;" : "=l"(ud.u) : "l"(ua.u), "l"(ub.u), "l"(uc.u));
    return ud.f;
}
__device__ __forceinline__ float tanh_fast(float x) {
    float y;
    asm("tanh.approx.f32 %0, %1;" : "=f"(y) : "f"(x));
    return y;
}

// One hidden unit per thread, 3 LSTM elements per warp (lanes 0..29).
// 10-warp CTAs, grid=137 -> <=1 CTA/SM, uniform 10 warps/SM.
// h history kept in a 10-slot SMEM ring (slot = t mod 10). Gates read slot
// (t-1)%10 (warp-private broadcast). The output projection is ROTATED across
// the 10 j-lanes: every 10 steps, lane j projects h[t-j] from ring slot (9-j)
// (compile-time-constant slots inside a 20-step unrolled block) and stores
// out[t-j] directly (coalesced STG.32) -> projection cost amortized 10x and
// the per-step obuf/STG.128 path removed.
// Gates: f32x2 packed FMA chains; activations MUFU.TANH (sigmoid 0.5-scale
// folded into weights/biases). x via float4 with one-subblock prefetch.
__global__ void __launch_bounds__(320, 1) lstm_fused_kernel(
    const float* __restrict__ x,      // [B, T, 1]
    const float* __restrict__ W_ih,   // [4H, 1]
    const float* __restrict__ W_hh,   // [4H, H]
    const float* __restrict__ b_ih,   // [4H]
    const float* __restrict__ b_hh,   // [4H]
    const float* __restrict__ W_out,  // [1, H]
    const float* __restrict__ b_out,  // [1]
    float* __restrict__ out)          // [B, T, 1]
{
    // flat ring: [slot][warp(10) x ew(4) x 12]
    __shared__ float ring[NSLOT * SLOTF];

    const int tid  = threadIdx.x;
    const int lane = tid & 31;
    const int w    = tid >> 5;

    int ew = lane / HH;              // 0..2 element, 3 = idle lanes 30,31
    int j  = lane - ew * HH;         // hidden unit 0..9 (idle lanes: 0,1)
    const bool active = (ew < 3);

    int b = (blockIdx.x * 10 + w) * 3 + ew;
    const bool valid = active && (b < BB);
    const int bb = valid ? b : 0;

    // zero slot 9 of this warp's region (h[-1] = 0 read at each block's k=0... only m=0 matters)
    for (int i = lane; i < 48; i += 32)
        ring[9 * SLOTF + w * 48 + i] = 0.0f;
    __syncwarp();

    // ---- per-thread constants (sigmoid gates pre-scaled by 0.5) ----
    float2 wi2[5], wf2[5], wg2[5], wo2[5], wout2[5];
#pragma unroll
    for (int m = 0; m < 5; m++) {
        wi2[m] = make_float2(0.5f * W_hh[(0 * HH + j) * HH + 2 * m],
                             0.5f * W_hh[(0 * HH + j) * HH + 2 * m + 1]);
        wf2[m] = make_float2(0.5f * W_hh[(1 * HH + j) * HH + 2 * m],
                             0.5f * W_hh[(1 * HH + j) * HH + 2 * m + 1]);
        wg2[m] = make_float2(W_hh[(2 * HH + j) * HH + 2 * m],
                             W_hh[(2 * HH + j) * HH + 2 * m + 1]);
        wo2[m] = make_float2(0.5f * W_hh[(3 * HH + j) * HH + 2 * m],
                             0.5f * W_hh[(3 * HH + j) * HH + 2 * m + 1]);
        wout2[m] = make_float2(W_out[2 * m], W_out[2 * m + 1]);
    }
    const float2 wxi2 = make_float2(0.5f * W_ih[0 * HH + j], 0.0f);
    const float2 wxf2 = make_float2(0.5f * W_ih[1 * HH + j], 0.0f);
    const float2 wxg2 = make_float2(       W_ih[2 * HH + j], 0.0f);
    const float2 wxo2 = make_float2(0.5f * W_ih[3 * HH + j], 0.0f);
    const float2 bi2 = make_float2(0.5f * (b_ih[0 * HH + j] + b_hh[0 * HH + j]), 0.0f);
    const float2 bf2 = make_float2(0.5f * (b_ih[1 * HH + j] + b_hh[1 * HH + j]), 0.0f);
    const float2 bg2 = make_float2(       (b_ih[2 * HH + j] + b_hh[2 * HH + j]), 0.0f);
    const float2 bo2 = make_float2(0.5f * (b_ih[3 * HH + j] + b_hh[3 * HH + j]), 0.0f);
    const float2 bout2 = make_float2(b_out[0], 0.0f);

    const float* xp = x   + (size_t)bb * TT;
    float*       op = out + (size_t)bb * TT;

    // ring pointers (warp/element private region = 48 floats per slot)
    const float* rg = ring + w * 48 + ew * 12;        // slot-0 gate-read base
    float*       wb = ring + w * 48 + ew * 12 + j;    // slot-0 write addr
    // projection base: lane j reads slot (9-j) (same for both in-block proj points)
    const float* pr = ring + (9 - j) * SLOTF + w * 48 + ew * 12;
    // tail projection: lane j<8 reads slot (7-j)
    const int st = (j < 8) ? (7 - j) : 0;
    const float* prt = ring + st * SLOTF + w * 48 + ew * 12;
    // per-lane store pointer: proj1 of block m stores sp[20m], proj2 sp[20m+10]
    float* sp = op + (9 - j);

    float c = 0.0f;

    // One LSTM step: reads h[t-1] at rd, writes h[t] at wr. No projection.
    auto step = [&](float xv, const float* rd, float* wr) {
        float4 A  = *(const float4*)rd;
        float4 Bv = *(const float4*)(rd + 4);
        float2 C  = *(const float2*)(rd + 8);
        float2 hh2[5] = { make_float2(A.x, A.y), make_float2(A.z, A.w),
                          make_float2(Bv.x, Bv.y), make_float2(Bv.z, Bv.w), C };
        float2 x2 = make_float2(xv, xv);
        float2 aI = ffma2(x2, wxi2, bi2);
        float2 aF = ffma2(x2, wxf2, bf2);
        float2 aG = ffma2(x2, wxg2, bg2);
        float2 aO = ffma2(x2, wxo2, bo2);
#pragma unroll
        for (int m = 0; m < 5; m++) {
            aI = ffma2(hh2[m], wi2[m], aI);
            aF = ffma2(hh2[m], wf2[m], aF);
            aG = ffma2(hh2[m], wg2[m], aG);
            aO = ffma2(hh2[m], wo2[m], aO);
        }
        float si = fmaf(tanh_fast(aI.x + aI.y), 0.5f, 0.5f);
        float sf = fmaf(tanh_fast(aF.x + aF.y), 0.5f, 0.5f);
        float g  =      tanh_fast(aG.x + aG.y);
        float so = fmaf(tanh_fast(aO.x + aO.y), 0.5f, 0.5f);
        c = fmaf(sf, c, si * g);
        float h = so * tanh_fast(c);
        *wr = h;   // in-order per-warp SMEM pipe
    };

    // Projection of the h-vector at pr (lane-specific ring slot).
    auto proj = [&](const float* p) -> float {
        float4 A  = *(const float4*)p;
        float4 Bv = *(const float4*)(p + 4);
        float2 C  = *(const float2*)(p + 8);
        float2 oacc = ffma2(make_float2(A.x, A.y), wout2[0], bout2);
        oacc = ffma2(make_float2(A.z, A.w), wout2[1], oacc);
        oacc = ffma2(make_float2(Bv.x, Bv.y), wout2[2], oacc);
        oacc = ffma2(make_float2(Bv.z, Bv.w), wout2[3], oacc);
        oacc = ffma2(C, wout2[4], oacc);
        return oacc.x + oacc.y;
    };

#define RD(s) (rg + (s) * SLOTF)
#define WRS(s) (wb + (s) * SLOTF)

    // ---- 102 blocks of 20 steps (t = 0..2039) ----
    float4 x4 = *(const float4*)xp;
    float4 xn4;
    for (int m = 0; m < 102; m++) {
        const float* xq = xp + 20 * m;
        float* spm = sp + 20 * m;
        xn4 = *(const float4*)(xq + 4);
        step(x4.x, RD(9), WRS(0));
        step(x4.y, RD(0), WRS(1));
        step(x4.z, RD(1), WRS(2));
        step(x4.w, RD(2), WRS(3));
        x4 = xn4; xn4 = *(const float4*)(xq + 8);
        step(x4.x, RD(3), WRS(4));
        step(x4.y, RD(4), WRS(5));
        step(x4.z, RD(5), WRS(6));
        step(x4.w, RD(6), WRS(7));
        x4 = xn4; xn4 = *(const float4*)(xq + 12);
        step(x4.x, RD(7), WRS(8));
        step(x4.y, RD(8), WRS(9));
        {   // projection point 1: out[20m .. 20m+9], lane j -> out[20m+9-j]
            float po = proj(pr);
            if (valid) spm[0] = po;
        }
        step(x4.z, RD(9), WRS(0));
        step(x4.w, RD(0), WRS(1));
        x4 = xn4; xn4 = *(const float4*)(xq + 16);
        step(x4.x, RD(1), WRS(2));
        step(x4.y, RD(2), WRS(3));
        step(x4.z, RD(3), WRS(4));
        step(x4.w, RD(4), WRS(5));
        x4 = xn4; xn4 = *(const float4*)(xq + 20);
        step(x4.x, RD(5), WRS(6));
        step(x4.y, RD(6), WRS(7));
        step(x4.z, RD(7), WRS(8));
        step(x4.w, RD(8), WRS(9));
        {   // projection point 2: out[20m+10 .. 20m+19]
            float po = proj(pr);
            if (valid) spm[10] = po;
        }
        x4 = xn4;
    }

    // ---- tail: t = 2040..2047 (x4 holds x[2040..2043]) ----
    xn4 = *(const float4*)(xp + 2044);
    step(x4.x, RD(9), WRS(0));
    step(x4.y, RD(0), WRS(1));
    step(x4.z, RD(1), WRS(2));
    step(x4.w, RD(2), WRS(3));
    x4 = xn4;
    step(x4.x, RD(3), WRS(4));
    step(x4.y, RD(4), WRS(5));
    step(x4.z, RD(5), WRS(6));
    step(x4.w, RD(6), WRS(7));
    {   // final projection: lanes j<8 -> out[2047-j] = sp[2038]
        float po = proj(prt);
        if (valid && j < 8) sp[2038] = po;
    }
#undef RD
#undef WRS
}

extern "C" void kernel_launch(void* const* d_in, const int* in_sizes, int n_in,
                              void* d_out, int out_size) {
    const float* x     = (const float*)d_in[0];
    const float* W_ih  = (const float*)d_in[1];
    const float* W_hh  = (const float*)d_in[2];
    const float* b_ih  = (const float*)d_in[3];
    const float* b_hh  = (const float*)d_in[4];
    const float* W_out = (const float*)d_in[5];
    const float* b_out = (const float*)d_in[6];
    float* out = (float*)d_out;

    // 10-warp CTAs, 30 elements each: 137 CTAs -> <=1 CTA/SM, uniform 10 warps/SM
    const int elems_per_block = 30;
    const int grid = (BB + elems_per_block - 1) / elems_per_block;  // 137
    lstm_fused_kernel<<<grid, 320>>>(x, W_ih, W_hh, b_ih, b_hh, W_out, b_out, out);
}